// round 14
// baseline (speedup 1.0000x reference)
#include <cuda_runtime.h>
#include <cuda_bf16.h>
#include <cstdint>
#include <math.h>

static constexpr int Bv = 2;
static constexpr int Tv = 2048;
static constexpr int Cv = 2048;
static constexpr int Hv = 16;
static constexpr int HD = 128;
static constexpr int ROWS = Bv * Tv;  // 4096

__device__ float g_q[(size_t)Bv * Tv * Cv];
__device__ float g_k[(size_t)Bv * Tv * Cv];
__device__ float g_v[(size_t)Bv * Tv * Cv];
__device__ float g_attn[(size_t)Bv * Tv * Cv];
__device__ float g_proj[(size_t)Bv * Tv * Cv];
// pre-split bf16 hi/lo of (roped) K and V
__device__ __nv_bfloat16 g_khi[(size_t)Bv * Tv * Cv];
__device__ __nv_bfloat16 g_klo[(size_t)Bv * Tv * Cv];
__device__ __nv_bfloat16 g_vhi[(size_t)Bv * Tv * Cv];
__device__ __nv_bfloat16 g_vlo[(size_t)Bv * Tv * Cv];

// ---------------------------------------------------------------------------
// helpers
// ---------------------------------------------------------------------------
__device__ __forceinline__ unsigned smem_u32(const void* p) {
    return (unsigned)__cvta_generic_to_shared(p);
}

__device__ __forceinline__ unsigned f2tf32(float x) {
    unsigned r;
    asm("cvt.rna.tf32.f32 %0, %1;" : "=r"(r) : "f"(x));
    return r;
}

__device__ __forceinline__ void mma_tf32(float* d, const unsigned* a, const unsigned* b) {
    asm volatile(
        "mma.sync.aligned.m16n8k8.row.col.f32.tf32.tf32.f32 "
        "{%0,%1,%2,%3}, {%4,%5,%6,%7}, {%8,%9}, {%0,%1,%2,%3};"
        : "+f"(d[0]), "+f"(d[1]), "+f"(d[2]), "+f"(d[3])
        : "r"(a[0]), "r"(a[1]), "r"(a[2]), "r"(a[3]), "r"(b[0]), "r"(b[1]));
}

__device__ __forceinline__ void mma_bf16(float* d, const unsigned* a, const unsigned* b) {
    asm volatile(
        "mma.sync.aligned.m16n8k16.row.col.f32.bf16.bf16.f32 "
        "{%0,%1,%2,%3}, {%4,%5,%6,%7}, {%8,%9}, {%0,%1,%2,%3};"
        : "+f"(d[0]), "+f"(d[1]), "+f"(d[2]), "+f"(d[3])
        : "r"(a[0]), "r"(a[1]), "r"(a[2]), "r"(a[3]), "r"(b[0]), "r"(b[1]));
}

__device__ __forceinline__ void ldmatrix_x2_trans(unsigned& r0, unsigned& r1, unsigned addr) {
    asm volatile("ldmatrix.sync.aligned.m8n8.x2.trans.shared.b16 {%0,%1}, [%2];"
                 : "=r"(r0), "=r"(r1) : "r"(addr));
}

__device__ __forceinline__ void split_bf16(float x, __nv_bfloat16& h, __nv_bfloat16& l) {
    h = __float2bfloat16_rn(x);
    l = __float2bfloat16_rn(x - __bfloat162float(h));
}

__device__ __forceinline__ void splitpack_bf16(float v0, float v1,
                                               unsigned& hi, unsigned& lo) {
    __nv_bfloat16 h0, l0, h1, l1;
    split_bf16(v0, h0, l0);
    split_bf16(v1, h1, l1);
    hi = (unsigned)__bfloat16_as_ushort(h0) | ((unsigned)__bfloat16_as_ushort(h1) << 16);
    lo = (unsigned)__bfloat16_as_ushort(l0) | ((unsigned)__bfloat16_as_ushort(l1) << 16);
}

// ---------------------------------------------------------------------------
// TF32 tensor-core GEMM, double-buffered smem, ONE sync per K-tile.
// Staggered prefetch keeps only 16 prefetch regs live at a time:
//   sync; [load A(i+1)]; MMA k8=0,1; [store A(i+1), load B(i+1)];
//   MMA k8=2,3; [store B(i+1)]
// C[m][n] = sum_k A[m*K+k] * B[n*K+k]  (NT, K-major). Numerics identical to R5.
// ---------------------------------------------------------------------------
static constexpr int GEMM_SMEM_BYTES = 4 * 128 * 36 * 4;  // 73728

__device__ __forceinline__ void gemm_store_tile(
    float* buf, const float4* p, const int* lrow, const int* lc4)
{
#pragma unroll
    for (int it = 0; it < 4; ++it) {
        float* dst = &buf[lrow[it] * 36 + lc4[it]];
        dst[0] = __uint_as_float(f2tf32(p[it].x));
        dst[1] = __uint_as_float(f2tf32(p[it].y));
        dst[2] = __uint_as_float(f2tf32(p[it].z));
        dst[3] = __uint_as_float(f2tf32(p[it].w));
    }
}

__device__ __forceinline__ void tf32_gemm_body(
    const float* __restrict__ A, const float* __restrict__ B,
    float* __restrict__ C, int M, int N, int K, float* gsm)
{
    float* Ab[2] = {gsm, gsm + 4608};
    float* Bb[2] = {gsm + 9216, gsm + 13824};

    const int tid = threadIdx.x;
    const int bm = blockIdx.y * 128;
    const int bn = blockIdx.x * 128;

    const int w = tid >> 5;
    const int wr = w >> 2;
    const int wc = w & 3;
    const int lane = tid & 31;
    const int qr = lane >> 2;
    const int qc = lane & 3;

    int lrow[4], lc4[4];
#pragma unroll
    for (int it = 0; it < 4; ++it) {
        int lin = tid + it * 256;
        lrow[it] = lin >> 3;
        lc4[it] = (lin & 7) << 2;
    }

    // prologue: tile 0 -> buf 0
    {
        float4 pa[4], pb[4];
#pragma unroll
        for (int it = 0; it < 4; ++it) {
            pa[it] = *(const float4*)(A + (size_t)(bm + lrow[it]) * K + lc4[it]);
            pb[it] = *(const float4*)(B + (size_t)(bn + lrow[it]) * K + lc4[it]);
        }
        gemm_store_tile(Ab[0], pa, lrow, lc4);
        gemm_store_tile(Bb[0], pb, lrow, lc4);
    }

    float acc[4][4][4];
#pragma unroll
    for (int mt = 0; mt < 4; ++mt)
#pragma unroll
        for (int nt = 0; nt < 4; ++nt)
#pragma unroll
            for (int i = 0; i < 4; ++i) acc[mt][nt][i] = 0.f;

    const int nkt = K >> 5;  // 64
    for (int i = 0; i < nkt; ++i) {
        __syncthreads();  // buf[i&1] ready; buf[(i+1)&1] fully consumed
        const float* As = Ab[i & 1];
        const float* Bs = Bb[i & 1];
        const bool hn = (i + 1 < nkt);
        const int kt = (i + 1) << 5;

        float4 pf[4];
        if (hn) {
#pragma unroll
            for (int it = 0; it < 4; ++it)
                pf[it] = *(const float4*)(A + (size_t)(bm + lrow[it]) * K + kt + lc4[it]);
        }

        // ---- MMA k8 = 0,1 (overlaps A prefetch latency) ----
#pragma unroll
        for (int k8 = 0; k8 < 2; ++k8) {
            const int k0 = k8 * 8;
            unsigned afr[4][4];
#pragma unroll
            for (int mt = 0; mt < 4; ++mt) {
                int r0 = wr * 64 + mt * 16 + qr;
                afr[mt][0] = __float_as_uint(As[r0 * 36 + k0 + qc]);
                afr[mt][1] = __float_as_uint(As[(r0 + 8) * 36 + k0 + qc]);
                afr[mt][2] = __float_as_uint(As[r0 * 36 + k0 + qc + 4]);
                afr[mt][3] = __float_as_uint(As[(r0 + 8) * 36 + k0 + qc + 4]);
            }
            unsigned bfr[4][2];
#pragma unroll
            for (int nt = 0; nt < 4; ++nt) {
                int n0 = wc * 32 + nt * 8 + qr;
                bfr[nt][0] = __float_as_uint(Bs[n0 * 36 + k0 + qc]);
                bfr[nt][1] = __float_as_uint(Bs[n0 * 36 + k0 + qc + 4]);
            }
#pragma unroll
            for (int mt = 0; mt < 4; ++mt)
#pragma unroll
                for (int nt = 0; nt < 4; ++nt)
                    mma_tf32(acc[mt][nt], afr[mt], bfr[nt]);
        }

        if (hn) {
            gemm_store_tile(Ab[(i + 1) & 1], pf, lrow, lc4);  // retire A regs
#pragma unroll
            for (int it = 0; it < 4; ++it)
                pf[it] = *(const float4*)(B + (size_t)(bn + lrow[it]) * K + kt + lc4[it]);
        }

        // ---- MMA k8 = 2,3 (overlaps B prefetch latency) ----
#pragma unroll
        for (int k8 = 2; k8 < 4; ++k8) {
            const int k0 = k8 * 8;
            unsigned afr[4][4];
#pragma unroll
            for (int mt = 0; mt < 4; ++mt) {
                int r0 = wr * 64 + mt * 16 + qr;
                afr[mt][0] = __float_as_uint(As[r0 * 36 + k0 + qc]);
                afr[mt][1] = __float_as_uint(As[(r0 + 8) * 36 + k0 + qc]);
                afr[mt][2] = __float_as_uint(As[r0 * 36 + k0 + qc + 4]);
                afr[mt][3] = __float_as_uint(As[(r0 + 8) * 36 + k0 + qc + 4]);
            }
            unsigned bfr[4][2];
#pragma unroll
            for (int nt = 0; nt < 4; ++nt) {
                int n0 = wc * 32 + nt * 8 + qr;
                bfr[nt][0] = __float_as_uint(Bs[n0 * 36 + k0 + qc]);
                bfr[nt][1] = __float_as_uint(Bs[n0 * 36 + k0 + qc + 4]);
            }
#pragma unroll
            for (int mt = 0; mt < 4; ++mt)
#pragma unroll
                for (int nt = 0; nt < 4; ++nt)
                    mma_tf32(acc[mt][nt], afr[mt], bfr[nt]);
        }

        if (hn)
            gemm_store_tile(Bb[(i + 1) & 1], pf, lrow, lc4);
    }

#pragma unroll
    for (int mt = 0; mt < 4; ++mt) {
#pragma unroll
        for (int nt = 0; nt < 4; ++nt) {
            int row = bm + wr * 64 + mt * 16 + qr;
            int col = bn + wc * 32 + nt * 8 + 2 * qc;
            *(float2*)(C + (size_t)row * N + col) =
                make_float2(acc[mt][nt][0], acc[mt][nt][1]);
            *(float2*)(C + (size_t)(row + 8) * N + col) =
                make_float2(acc[mt][nt][2], acc[mt][nt][3]);
        }
    }
}

__global__ __launch_bounds__(256, 2) void tf32_gemm_nt(
    const float* __restrict__ A, const float* __restrict__ B,
    float* __restrict__ C, int M, int N, int K)
{
    extern __shared__ float gsm[];
    tf32_gemm_body(A, B, C, M, N, K, gsm);
}

__global__ __launch_bounds__(256, 2) void tf32_gemm_qkv(
    const float* __restrict__ x,
    const float* __restrict__ Wq, const float* __restrict__ Wk,
    const float* __restrict__ Wv,
    float* __restrict__ q, float* __restrict__ k, float* __restrict__ v,
    int M, int N, int K)
{
    extern __shared__ float gsm[];
    const float* B = (blockIdx.z == 0) ? Wq : (blockIdx.z == 1) ? Wk : Wv;
    float* C = (blockIdx.z == 0) ? q : (blockIdx.z == 1) ? k : v;
    tf32_gemm_body(x, B, C, M, N, K, gsm);
}

// ---------------------------------------------------------------------------
// RoPE on q (in-place fp32) and k (-> bf16 hi/lo); V convert (-> bf16 hi/lo).
// ---------------------------------------------------------------------------
__global__ void rope_split_kernel(
    float* __restrict__ q, const float* __restrict__ k, const float* __restrict__ v,
    __nv_bfloat16* __restrict__ khi, __nv_bfloat16* __restrict__ klo,
    __nv_bfloat16* __restrict__ vhi, __nv_bfloat16* __restrict__ vlo)
{
    const int idx = blockIdx.x;
    const int h = idx % Hv;
    const int t = (idx / Hv) % Tv;
    const int b = idx / (Hv * Tv);
    const int d = threadIdx.x;  // 0..63

    const float e = (2.0f * (float)d) / (float)HD;
    const float inv_freq = 1.0f / powf(10000.0f, e);
    const float ang = (float)t * inv_freq;
    float s, c;
    sincosf(ang, &s, &c);

    const size_t base = ((size_t)(b * Tv + t)) * Cv + (size_t)h * HD;

    float q0 = q[base + d], q1 = q[base + d + 64];
    q[base + d]      = q0 * c - q1 * s;
    q[base + d + 64] = q1 * c + q0 * s;

    float k0 = k[base + d], k1 = k[base + d + 64];
    float kr0 = k0 * c - k1 * s;
    float kr1 = k1 * c + k0 * s;
    __nv_bfloat16 hh, ll;
    split_bf16(kr0, hh, ll);
    khi[base + d] = hh; klo[base + d] = ll;
    split_bf16(kr1, hh, ll);
    khi[base + d + 64] = hh; klo[base + d + 64] = ll;

    float v0 = v[base + d], v1 = v[base + d + 64];
    split_bf16(v0, hh, ll);
    vhi[base + d] = hh; vlo[base + d] = ll;
    split_bf16(v1, hh, ll);
    vhi[base + d + 64] = hh; vlo[base + d + 64] = ll;
}

// ---------------------------------------------------------------------------
// Causal flash attention (R12 version — known good).
// bf16 m16n8k16 hi/lo, 64-row q-tiles, pre-split K/V from gmem, heavy-first.
// ---------------------------------------------------------------------------
static constexpr int QK_PITCH = 136;  // halves per row (b32 pitch 68)
static constexpr int P_PITCH = 72;    // halves per row (b32 pitch 36)
static constexpr int SZ_QK = 64 * QK_PITCH;
static constexpr int FA_SMEM_BYTES =
    6 * SZ_QK * 2 + 64 * 68 * 4 + 2 * 64 * P_PITCH * 2 + 3 * 64 * 4;  // 141056

__global__ __launch_bounds__(256) void flash_attn_bf16(
    const float* __restrict__ q,
    const __nv_bfloat16* __restrict__ khi, const __nv_bfloat16* __restrict__ klo,
    const __nv_bfloat16* __restrict__ vhi, const __nv_bfloat16* __restrict__ vlo,
    float* __restrict__ o)
{
    extern __shared__ char smbase[];
    __nv_bfloat16* Qhi = (__nv_bfloat16*)smbase;
    __nv_bfloat16* Qlo = Qhi + SZ_QK;
    __nv_bfloat16* Khi = Qlo + SZ_QK;
    __nv_bfloat16* Klo = Khi + SZ_QK;
    __nv_bfloat16* Vhi = Klo + SZ_QK;
    __nv_bfloat16* Vlo = Vhi + SZ_QK;
    float* Ss = (float*)(Vlo + SZ_QK);            // 64 x 68 fp32
    __nv_bfloat16* Ph = (__nv_bfloat16*)(Ss + 64 * 68);
    __nv_bfloat16* Pl = Ph + 64 * P_PITCH;
    float* mrow = (float*)(Pl + 64 * P_PITCH);
    float* lrow = mrow + 64;
    float* srow = lrow + 64;

    unsigned* Qhi32 = (unsigned*)Qhi;
    unsigned* Qlo32 = (unsigned*)Qlo;
    unsigned* Khi32 = (unsigned*)Khi;
    unsigned* Klo32 = (unsigned*)Klo;
    unsigned* Ph32 = (unsigned*)Ph;
    unsigned* Pl32 = (unsigned*)Pl;

    const int qb = gridDim.x - 1 - blockIdx.x;   // heavy blocks first
    const int h = blockIdx.y;
    const int b = blockIdx.z;
    const int tid = threadIdx.x;
    const int lane = tid & 31;
    const int qr = lane >> 2;
    const int qc = lane & 3;
    const int w = tid >> 5;
    const int wm = w >> 2;
    const int wn = w & 3;

    const size_t headoff = (size_t)h * HD;
    const float* qbase = q + ((size_t)b * Tv + (size_t)qb * 64) * Cv + headoff;

#pragma unroll
    for (int it = 0; it < 8; ++it) {
        int idx = tid + it * 256;
        int row = idx >> 5;
        int c4 = (idx & 31) << 2;
        float4 qv = *(const float4*)(qbase + (size_t)row * Cv + c4);
        unsigned h0, l0, h1, l1;
        splitpack_bf16(qv.x, qv.y, h0, l0);
        splitpack_bf16(qv.z, qv.w, h1, l1);
        int base = row * 68 + (c4 >> 1);
        Qhi32[base] = h0; Qhi32[base + 1] = h1;
        Qlo32[base] = l0; Qlo32[base + 1] = l1;
    }
    if (tid < 64) {
        mrow[tid] = -3.0e38f;
        lrow[tid] = 0.f;
    }

    float oacc[2][4][4];
#pragma unroll
    for (int mt = 0; mt < 2; ++mt)
#pragma unroll
        for (int nt = 0; nt < 4; ++nt)
#pragma unroll
            for (int i = 0; i < 4; ++i) oacc[mt][nt][i] = 0.f;

    const float sscale = 0.08838834764831845f;  // 1/sqrt(128)

    const int crow[4] = { (tid + 0) >> 4, (tid + 256) >> 4,
                          (tid + 512) >> 4, (tid + 768) >> 4 };
    const int cch[4] = { (tid + 0) & 15, (tid + 256) & 15,
                         (tid + 512) & 15, (tid + 768) & 15 };

    for (int jt = 0; jt <= qb; ++jt) {
        __syncthreads();
        const size_t tbase = ((size_t)b * Tv + (size_t)jt * 64) * Cv + headoff;
        const __nv_bfloat16* khb = khi + tbase;
        const __nv_bfloat16* klb = klo + tbase;
        const __nv_bfloat16* vhb = vhi + tbase;
        const __nv_bfloat16* vlb = vlo + tbase;
#pragma unroll
        for (int it = 0; it < 4; ++it) {
            int row = crow[it];
            int ch = cch[it];
            size_t goff = (size_t)row * Cv + ch * 8;
            int soff = row * 68 + ch * 4;
            *(uint4*)&Khi32[soff] = *(const uint4*)(khb + goff);
            *(uint4*)&Klo32[soff] = *(const uint4*)(klb + goff);
            *(uint4*)((__nv_bfloat16*)Vhi + row * QK_PITCH + ch * 8) =
                *(const uint4*)(vhb + goff);
            *(uint4*)((__nv_bfloat16*)Vlo + row * QK_PITCH + ch * 8) =
                *(const uint4*)(vlb + goff);
        }
        __syncthreads();

        // ---- S = Q K^T, bf16 3-pass over k=128 (8 k16 steps) ----
        float sacc[2][2][4];
#pragma unroll
        for (int mt = 0; mt < 2; ++mt)
#pragma unroll
            for (int nt = 0; nt < 2; ++nt)
#pragma unroll
                for (int i = 0; i < 4; ++i) sacc[mt][nt][i] = 0.f;

#pragma unroll
        for (int t = 0; t < 8; ++t) {
            unsigned qh[2][4], ql[2][4];
#pragma unroll
            for (int mt = 0; mt < 2; ++mt) {
                int r0 = wm * 32 + mt * 16;
                int b0 = (r0 + qr) * 68 + t * 8 + qc;
                int b1 = (r0 + 8 + qr) * 68 + t * 8 + qc;
                qh[mt][0] = Qhi32[b0]; qh[mt][1] = Qhi32[b1];
                qh[mt][2] = Qhi32[b0 + 4]; qh[mt][3] = Qhi32[b1 + 4];
                ql[mt][0] = Qlo32[b0]; ql[mt][1] = Qlo32[b1];
                ql[mt][2] = Qlo32[b0 + 4]; ql[mt][3] = Qlo32[b1 + 4];
            }
            unsigned kh[2][2], kl[2][2];
#pragma unroll
            for (int nt = 0; nt < 2; ++nt) {
                int n0 = wn * 16 + nt * 8;
                int bb = (n0 + qr) * 68 + t * 8 + qc;
                kh[nt][0] = Khi32[bb]; kh[nt][1] = Khi32[bb + 4];
                kl[nt][0] = Klo32[bb]; kl[nt][1] = Klo32[bb + 4];
            }
#pragma unroll
            for (int mt = 0; mt < 2; ++mt)
#pragma unroll
                for (int nt = 0; nt < 2; ++nt) {
                    mma_bf16(sacc[mt][nt], qh[mt], kh[nt]);
                    mma_bf16(sacc[mt][nt], qh[mt], kl[nt]);
                    mma_bf16(sacc[mt][nt], ql[mt], kh[nt]);
                }
        }

        // ---- scale + causal mask + stage S (fp32) ----
#pragma unroll
        for (int mt = 0; mt < 2; ++mt) {
#pragma unroll
            for (int nt = 0; nt < 2; ++nt) {
                int row = wm * 32 + mt * 16 + qr;
                int col = wn * 16 + nt * 8 + 2 * qc;
                int rowg = qb * 64 + row;
                int colg = jt * 64 + col;
                float s0 = sacc[mt][nt][0] * sscale;
                float s1 = sacc[mt][nt][1] * sscale;
                float s2 = sacc[mt][nt][2] * sscale;
                float s3 = sacc[mt][nt][3] * sscale;
                if (colg > rowg) s0 = -1e30f;
                if (colg + 1 > rowg) s1 = -1e30f;
                if (colg > rowg + 8) s2 = -1e30f;
                if (colg + 1 > rowg + 8) s3 = -1e30f;
                *(float2*)&Ss[row * 68 + col] = make_float2(s0, s1);
                *(float2*)&Ss[(row + 8) * 68 + col] = make_float2(s2, s3);
            }
        }
        __syncthreads();

        // ---- online softmax, 4 threads per row; P split to bf16 hi/lo ----
        {
            int r = tid >> 2;
            int part = tid & 3;
            float* srP = &Ss[r * 68 + part * 16];
            __nv_bfloat16* php = &Ph[r * P_PITCH + part * 16];
            __nv_bfloat16* plp = &Pl[r * P_PITCH + part * 16];
            float mx = -3.0e38f;
#pragma unroll
            for (int j = 0; j < 16; ++j) mx = fmaxf(mx, srP[j]);
            mx = fmaxf(mx, __shfl_xor_sync(0xffffffffu, mx, 1));
            mx = fmaxf(mx, __shfl_xor_sync(0xffffffffu, mx, 2));
            float mo = mrow[r];
            float mn = fmaxf(mo, mx);
            float ls = 0.f;
#pragma unroll
            for (int j = 0; j < 16; ++j) {
                float p = __expf(srP[j] - mn);
                __nv_bfloat16 ph, pl;
                split_bf16(p, ph, pl);
                php[j] = ph;
                plp[j] = pl;
                ls += p;
            }
            ls += __shfl_xor_sync(0xffffffffu, ls, 1);
            ls += __shfl_xor_sync(0xffffffffu, ls, 2);
            if (part == 0) {
                float sc = __expf(mo - mn);
                lrow[r] = lrow[r] * sc + ls;
                mrow[r] = mn;
                srow[r] = sc;
            }
        }
        __syncthreads();

        // ---- rescale O, then O += P V (bf16 3-pass over k=64) ----
#pragma unroll
        for (int mt = 0; mt < 2; ++mt) {
            int r0 = wm * 32 + mt * 16;
            float sc0 = srow[r0 + qr];
            float sc1 = srow[r0 + 8 + qr];
#pragma unroll
            for (int nt = 0; nt < 4; ++nt) {
                oacc[mt][nt][0] *= sc0;
                oacc[mt][nt][1] *= sc0;
                oacc[mt][nt][2] *= sc1;
                oacc[mt][nt][3] *= sc1;
            }
        }

#pragma unroll
        for (int t = 0; t < 4; ++t) {
            unsigned ph[2][4], pl[2][4];
#pragma unroll
            for (int mt = 0; mt < 2; ++mt) {
                int r0 = wm * 32 + mt * 16;
                int b0 = (r0 + qr) * 36 + t * 8 + qc;
                int b1 = (r0 + 8 + qr) * 36 + t * 8 + qc;
                ph[mt][0] = Ph32[b0]; ph[mt][1] = Ph32[b1];
                ph[mt][2] = Ph32[b0 + 4]; ph[mt][3] = Ph32[b1 + 4];
                pl[mt][0] = Pl32[b0]; pl[mt][1] = Pl32[b1];
                pl[mt][2] = Pl32[b0 + 4]; pl[mt][3] = Pl32[b1 + 4];
            }
            int vrow = 16 * t + (lane & 15);
#pragma unroll
            for (int nt = 0; nt < 4; ++nt) {
                int n0 = wn * 32 + nt * 8;
                unsigned vh[2], vl[2];
                ldmatrix_x2_trans(vh[0], vh[1],
                                  smem_u32(&Vhi[vrow * QK_PITCH + n0]));
                ldmatrix_x2_trans(vl[0], vl[1],
                                  smem_u32(&Vlo[vrow * QK_PITCH + n0]));
#pragma unroll
                for (int mt = 0; mt < 2; ++mt) {
                    mma_bf16(oacc[mt][nt], ph[mt], vh);
                    mma_bf16(oacc[mt][nt], ph[mt], vl);
                    mma_bf16(oacc[mt][nt], pl[mt], vh);
                }
            }
        }
    }

    // ---- epilogue: normalize and store ----
    float* obase = o + ((size_t)b * Tv + (size_t)qb * 64) * Cv + headoff;
#pragma unroll
    for (int mt = 0; mt < 2; ++mt) {
        int r0 = wm * 32 + mt * 16;
        float inv0 = 1.f / lrow[r0 + qr];
        float inv1 = 1.f / lrow[r0 + 8 + qr];
#pragma unroll
        for (int nt = 0; nt < 4; ++nt) {
            int col = wn * 32 + nt * 8 + 2 * qc;
            *(float2*)(obase + (size_t)(r0 + qr) * Cv + col) =
                make_float2(oacc[mt][nt][0] * inv0, oacc[mt][nt][1] * inv0);
            *(float2*)(obase + (size_t)(r0 + 8 + qr) * Cv + col) =
                make_float2(oacc[mt][nt][2] * inv1, oacc[mt][nt][3] * inv1);
        }
    }
}

// ---------------------------------------------------------------------------
// LayerNorm over last dim (2048) per row.
// ---------------------------------------------------------------------------
__global__ __launch_bounds__(256) void layernorm_kernel(
    const float* __restrict__ in, const float* __restrict__ gamma,
    const float* __restrict__ beta, float* __restrict__ out)
{
    __shared__ float ws[8], ws2[8];
    const int row = blockIdx.x;
    const int t = threadIdx.x;
    const float* p = in + (size_t)row * Cv;

    float4 x0 = *(const float4*)(p + t * 8);
    float4 x1 = *(const float4*)(p + t * 8 + 4);
    float s = x0.x + x0.y + x0.z + x0.w + x1.x + x1.y + x1.z + x1.w;
    float s2 = x0.x * x0.x + x0.y * x0.y + x0.z * x0.z + x0.w * x0.w +
               x1.x * x1.x + x1.y * x1.y + x1.z * x1.z + x1.w * x1.w;

#pragma unroll
    for (int off = 16; off > 0; off >>= 1) {
        s += __shfl_xor_sync(0xffffffffu, s, off);
        s2 += __shfl_xor_sync(0xffffffffu, s2, off);
    }
    const int wid = t >> 5, lid = t & 31;
    if (lid == 0) { ws[wid] = s; ws2[wid] = s2; }
    __syncthreads();
    if (t == 0) {
        float a = 0.f, a2 = 0.f;
#pragma unroll
        for (int i = 0; i < 8; ++i) { a += ws[i]; a2 += ws2[i]; }
        ws[0] = a; ws2[0] = a2;
    }
    __syncthreads();
    const float mu = ws[0] / (float)Cv;
    const float var = ws2[0] / (float)Cv - mu * mu;
    const float inv = rsqrtf(var + 1e-5f);

    float4 g0 = *(const float4*)(gamma + t * 8);
    float4 g1 = *(const float4*)(gamma + t * 8 + 4);
    float4 b0 = *(const float4*)(beta + t * 8);
    float4 b1 = *(const float4*)(beta + t * 8 + 4);
    float4 o0, o1;
    o0.x = (x0.x - mu) * inv * g0.x + b0.x;
    o0.y = (x0.y - mu) * inv * g0.y + b0.y;
    o0.z = (x0.z - mu) * inv * g0.z + b0.z;
    o0.w = (x0.w - mu) * inv * g0.w + b0.w;
    o1.x = (x1.x - mu) * inv * g1.x + b1.x;
    o1.y = (x1.y - mu) * inv * g1.y + b1.y;
    o1.z = (x1.z - mu) * inv * g1.z + b1.z;
    o1.w = (x1.w - mu) * inv * g1.w + b1.w;
    *(float4*)(out + (size_t)row * Cv + t * 8) = o0;
    *(float4*)(out + (size_t)row * Cv + t * 8 + 4) = o1;
}

// ---------------------------------------------------------------------------
extern "C" void kernel_launch(void* const* d_in, const int* in_sizes, int n_in,
                              void* d_out, int out_size)
{
    const float* x  = (const float*)d_in[0];
    const float* Wq = (const float*)d_in[1];
    const float* Wk = (const float*)d_in[2];
    const float* Wv = (const float*)d_in[3];
    const float* Wo = (const float*)d_in[4];
    const float* gm = (const float*)d_in[5];
    const float* bt = (const float*)d_in[6];
    float* out = (float*)d_out;

    float *qp, *kp, *vp, *ap, *pp;
    __nv_bfloat16 *khp, *klp, *vhp, *vlp;
    cudaGetSymbolAddress((void**)&qp, g_q);
    cudaGetSymbolAddress((void**)&kp, g_k);
    cudaGetSymbolAddress((void**)&vp, g_v);
    cudaGetSymbolAddress((void**)&ap, g_attn);
    cudaGetSymbolAddress((void**)&pp, g_proj);
    cudaGetSymbolAddress((void**)&khp, g_khi);
    cudaGetSymbolAddress((void**)&klp, g_klo);
    cudaGetSymbolAddress((void**)&vhp, g_vhi);
    cudaGetSymbolAddress((void**)&vlp, g_vlo);

    cudaFuncSetAttribute(tf32_gemm_nt,
                         cudaFuncAttributeMaxDynamicSharedMemorySize,
                         GEMM_SMEM_BYTES);
    cudaFuncSetAttribute(tf32_gemm_qkv,
                         cudaFuncAttributeMaxDynamicSharedMemorySize,
                         GEMM_SMEM_BYTES);
    cudaFuncSetAttribute(flash_attn_bf16,
                         cudaFuncAttributeMaxDynamicSharedMemorySize,
                         FA_SMEM_BYTES);

    dim3 qkvgrid(Cv / 128, ROWS / 128, 3);  // (16, 32, 3)
    tf32_gemm_qkv<<<qkvgrid, 256, GEMM_SMEM_BYTES>>>(x, Wq, Wk, Wv, qp, kp, vp,
                                                     ROWS, Cv, Cv);

    rope_split_kernel<<<Bv * Tv * Hv, 64>>>(qp, kp, vp, khp, klp, vhp, vlp);

    dim3 agrid(Tv / 64, Hv, Bv);  // (32, 16, 2)
    flash_attn_bf16<<<agrid, 256, FA_SMEM_BYTES>>>(qp, khp, klp, vhp, vlp, ap);

    dim3 ggrid(Cv / 128, ROWS / 128);  // (16, 32)
    tf32_gemm_nt<<<ggrid, 256, GEMM_SMEM_BYTES>>>(ap, Wo, pp, ROWS, Cv, Cv);
    layernorm_kernel<<<ROWS, 256>>>(pp, gm, bt, out);
}

// round 15
// speedup vs baseline: 1.3508x; 1.3508x over previous
#include <cuda_runtime.h>
#include <cuda_bf16.h>
#include <cstdint>
#include <math.h>

static constexpr int Bv = 2;
static constexpr int Tv = 2048;
static constexpr int Cv = 2048;
static constexpr int Hv = 16;
static constexpr int HD = 128;
static constexpr int ROWS = Bv * Tv;  // 4096

__device__ float g_q[(size_t)Bv * Tv * Cv];
__device__ float g_k[(size_t)Bv * Tv * Cv];
__device__ float g_v[(size_t)Bv * Tv * Cv];
__device__ float g_attn[(size_t)Bv * Tv * Cv];
__device__ float g_proj[(size_t)Bv * Tv * Cv];
// pre-split bf16 hi/lo of (roped) K and V
__device__ __nv_bfloat16 g_khi[(size_t)Bv * Tv * Cv];
__device__ __nv_bfloat16 g_klo[(size_t)Bv * Tv * Cv];
__device__ __nv_bfloat16 g_vhi[(size_t)Bv * Tv * Cv];
__device__ __nv_bfloat16 g_vlo[(size_t)Bv * Tv * Cv];

// ---------------------------------------------------------------------------
// helpers
// ---------------------------------------------------------------------------
__device__ __forceinline__ unsigned smem_u32(const void* p) {
    return (unsigned)__cvta_generic_to_shared(p);
}

__device__ __forceinline__ unsigned f2tf32(float x) {
    unsigned r;
    asm("cvt.rna.tf32.f32 %0, %1;" : "=r"(r) : "f"(x));
    return r;
}

__device__ __forceinline__ void mma_tf32(float* d, const unsigned* a, const unsigned* b) {
    asm volatile(
        "mma.sync.aligned.m16n8k8.row.col.f32.tf32.tf32.f32 "
        "{%0,%1,%2,%3}, {%4,%5,%6,%7}, {%8,%9}, {%0,%1,%2,%3};"
        : "+f"(d[0]), "+f"(d[1]), "+f"(d[2]), "+f"(d[3])
        : "r"(a[0]), "r"(a[1]), "r"(a[2]), "r"(a[3]), "r"(b[0]), "r"(b[1]));
}

__device__ __forceinline__ void mma_bf16(float* d, const unsigned* a, const unsigned* b) {
    asm volatile(
        "mma.sync.aligned.m16n8k16.row.col.f32.bf16.bf16.f32 "
        "{%0,%1,%2,%3}, {%4,%5,%6,%7}, {%8,%9}, {%0,%1,%2,%3};"
        : "+f"(d[0]), "+f"(d[1]), "+f"(d[2]), "+f"(d[3])
        : "r"(a[0]), "r"(a[1]), "r"(a[2]), "r"(a[3]), "r"(b[0]), "r"(b[1]));
}

__device__ __forceinline__ void ldmatrix_x2_trans(unsigned& r0, unsigned& r1, unsigned addr) {
    asm volatile("ldmatrix.sync.aligned.m8n8.x2.trans.shared.b16 {%0,%1}, [%2];"
                 : "=r"(r0), "=r"(r1) : "r"(addr));
}

__device__ __forceinline__ void cp_async16(unsigned smem_addr, const void* gptr) {
    asm volatile("cp.async.cg.shared.global [%0], [%1], 16;"
                 :: "r"(smem_addr), "l"(gptr));
}

__device__ __forceinline__ void split_bf16(float x, __nv_bfloat16& h, __nv_bfloat16& l) {
    h = __float2bfloat16_rn(x);
    l = __float2bfloat16_rn(x - __bfloat162float(h));
}

__device__ __forceinline__ void splitpack_bf16(float v0, float v1,
                                               unsigned& hi, unsigned& lo) {
    __nv_bfloat16 h0, l0, h1, l1;
    split_bf16(v0, h0, l0);
    split_bf16(v1, h1, l1);
    hi = (unsigned)__bfloat16_as_ushort(h0) | ((unsigned)__bfloat16_as_ushort(h1) << 16);
    lo = (unsigned)__bfloat16_as_ushort(l0) | ((unsigned)__bfloat16_as_ushort(l1) << 16);
}

// ---------------------------------------------------------------------------
// TF32 tensor-core GEMM (R12 version — known good 297us):
// C[m][n] = sum_k A[m*K+k] * B[n*K+k]  (NT, K-major), static smem, 2 syncs.
// ---------------------------------------------------------------------------
__device__ __forceinline__ void tf32_gemm_body(
    const float* __restrict__ A, const float* __restrict__ B,
    float* __restrict__ C, int M, int N, int K)
{
    __shared__ __align__(16) float As[128][36];
    __shared__ __align__(16) float Bs[128][36];

    const int tid = threadIdx.x;
    const int bm = blockIdx.y * 128;
    const int bn = blockIdx.x * 128;

    const int w = tid >> 5;
    const int wr = w >> 2;
    const int wc = w & 3;
    const int lane = tid & 31;
    const int qr = lane >> 2;
    const int qc = lane & 3;

    float4 pa[4], pb[4];
#pragma unroll
    for (int it = 0; it < 4; ++it) {
        int lin = tid + it * 256;
        int row = lin >> 3;
        int c4 = (lin & 7) << 2;
        pa[it] = *(const float4*)(A + (size_t)(bm + row) * K + c4);
        pb[it] = *(const float4*)(B + (size_t)(bn + row) * K + c4);
    }

    float acc[4][4][4];
#pragma unroll
    for (int mt = 0; mt < 4; ++mt)
#pragma unroll
        for (int nt = 0; nt < 4; ++nt)
#pragma unroll
            for (int i = 0; i < 4; ++i) acc[mt][nt][i] = 0.f;

    for (int kt = 0; kt < K; kt += 32) {
        __syncthreads();
#pragma unroll
        for (int it = 0; it < 4; ++it) {
            int lin = tid + it * 256;
            int row = lin >> 3;
            int c4 = (lin & 7) << 2;
            As[row][c4 + 0] = __uint_as_float(f2tf32(pa[it].x));
            As[row][c4 + 1] = __uint_as_float(f2tf32(pa[it].y));
            As[row][c4 + 2] = __uint_as_float(f2tf32(pa[it].z));
            As[row][c4 + 3] = __uint_as_float(f2tf32(pa[it].w));
            Bs[row][c4 + 0] = __uint_as_float(f2tf32(pb[it].x));
            Bs[row][c4 + 1] = __uint_as_float(f2tf32(pb[it].y));
            Bs[row][c4 + 2] = __uint_as_float(f2tf32(pb[it].z));
            Bs[row][c4 + 3] = __uint_as_float(f2tf32(pb[it].w));
        }
        __syncthreads();

        if (kt + 32 < K) {
#pragma unroll
            for (int it = 0; it < 4; ++it) {
                int lin = tid + it * 256;
                int row = lin >> 3;
                int c4 = (lin & 7) << 2;
                pa[it] = *(const float4*)(A + (size_t)(bm + row) * K + kt + 32 + c4);
                pb[it] = *(const float4*)(B + (size_t)(bn + row) * K + kt + 32 + c4);
            }
        }

#pragma unroll
        for (int k8 = 0; k8 < 4; ++k8) {
            const int k0 = k8 * 8;
            unsigned afr[4][4];
#pragma unroll
            for (int mt = 0; mt < 4; ++mt) {
                int r0 = wr * 64 + mt * 16 + qr;
                afr[mt][0] = __float_as_uint(As[r0][k0 + qc]);
                afr[mt][1] = __float_as_uint(As[r0 + 8][k0 + qc]);
                afr[mt][2] = __float_as_uint(As[r0][k0 + qc + 4]);
                afr[mt][3] = __float_as_uint(As[r0 + 8][k0 + qc + 4]);
            }
            unsigned bfr[4][2];
#pragma unroll
            for (int nt = 0; nt < 4; ++nt) {
                int n0 = wc * 32 + nt * 8 + qr;
                bfr[nt][0] = __float_as_uint(Bs[n0][k0 + qc]);
                bfr[nt][1] = __float_as_uint(Bs[n0][k0 + qc + 4]);
            }
#pragma unroll
            for (int mt = 0; mt < 4; ++mt)
#pragma unroll
                for (int nt = 0; nt < 4; ++nt)
                    mma_tf32(acc[mt][nt], afr[mt], bfr[nt]);
        }
    }

#pragma unroll
    for (int mt = 0; mt < 4; ++mt) {
#pragma unroll
        for (int nt = 0; nt < 4; ++nt) {
            int row = bm + wr * 64 + mt * 16 + qr;
            int col = bn + wc * 32 + nt * 8 + 2 * qc;
            *(float2*)(C + (size_t)row * N + col) =
                make_float2(acc[mt][nt][0], acc[mt][nt][1]);
            *(float2*)(C + (size_t)(row + 8) * N + col) =
                make_float2(acc[mt][nt][2], acc[mt][nt][3]);
        }
    }
}

__global__ __launch_bounds__(256) void tf32_gemm_nt(
    const float* __restrict__ A, const float* __restrict__ B,
    float* __restrict__ C, int M, int N, int K)
{
    tf32_gemm_body(A, B, C, M, N, K);
}

__global__ __launch_bounds__(256) void tf32_gemm_qkv(
    const float* __restrict__ x,
    const float* __restrict__ Wq, const float* __restrict__ Wk,
    const float* __restrict__ Wv,
    float* __restrict__ q, float* __restrict__ k, float* __restrict__ v,
    int M, int N, int K)
{
    const float* B = (blockIdx.z == 0) ? Wq : (blockIdx.z == 1) ? Wk : Wv;
    float* C = (blockIdx.z == 0) ? q : (blockIdx.z == 1) ? k : v;
    tf32_gemm_body(x, B, C, M, N, K);
}

// ---------------------------------------------------------------------------
// RoPE on q (in-place fp32) and k (-> bf16 hi/lo); V convert (-> bf16 hi/lo).
// ---------------------------------------------------------------------------
__global__ void rope_split_kernel(
    float* __restrict__ q, const float* __restrict__ k, const float* __restrict__ v,
    __nv_bfloat16* __restrict__ khi, __nv_bfloat16* __restrict__ klo,
    __nv_bfloat16* __restrict__ vhi, __nv_bfloat16* __restrict__ vlo)
{
    const int idx = blockIdx.x;
    const int h = idx % Hv;
    const int t = (idx / Hv) % Tv;
    const int b = idx / (Hv * Tv);
    const int d = threadIdx.x;  // 0..63

    const float e = (2.0f * (float)d) / (float)HD;
    const float inv_freq = 1.0f / powf(10000.0f, e);
    const float ang = (float)t * inv_freq;
    float s, c;
    sincosf(ang, &s, &c);

    const size_t base = ((size_t)(b * Tv + t)) * Cv + (size_t)h * HD;

    float q0 = q[base + d], q1 = q[base + d + 64];
    q[base + d]      = q0 * c - q1 * s;
    q[base + d + 64] = q1 * c + q0 * s;

    float k0 = k[base + d], k1 = k[base + d + 64];
    float kr0 = k0 * c - k1 * s;
    float kr1 = k1 * c + k0 * s;
    __nv_bfloat16 hh, ll;
    split_bf16(kr0, hh, ll);
    khi[base + d] = hh; klo[base + d] = ll;
    split_bf16(kr1, hh, ll);
    khi[base + d + 64] = hh; klo[base + d + 64] = ll;

    float v0 = v[base + d], v1 = v[base + d + 64];
    split_bf16(v0, hh, ll);
    vhi[base + d] = hh; vlo[base + d] = ll;
    split_bf16(v1, hh, ll);
    vhi[base + d + 64] = hh; vlo[base + d + 64] = ll;
}

// ---------------------------------------------------------------------------
// Causal flash attention, bf16 m16n8k16 hi/lo, 64-row q-tiles, heavy-first.
// KV tiles double-buffered via cp.async (zero register staging).
// 256 threads, 8 warps (2 m x 4 n).
// ---------------------------------------------------------------------------
static constexpr int QK_PITCH = 136;  // halves per row (b32 pitch 68)
static constexpr int P_PITCH = 72;    // halves per row (b32 pitch 36)
static constexpr int SZ_QK = 64 * QK_PITCH;   // halves per tile buffer
static constexpr int FA_SMEM_BYTES =
    2 * SZ_QK * 2 +            // Qhi, Qlo
    8 * SZ_QK * 2 +            // Khi/Klo/Vhi/Vlo x 2 buffers
    64 * 68 * 4 +              // Ss
    2 * 64 * P_PITCH * 2 +     // Ph, Pl
    3 * 64 * 4;                // mrow/lrow/srow   = 210688

__global__ __launch_bounds__(256) void flash_attn_bf16(
    const float* __restrict__ q,
    const __nv_bfloat16* __restrict__ khi, const __nv_bfloat16* __restrict__ klo,
    const __nv_bfloat16* __restrict__ vhi, const __nv_bfloat16* __restrict__ vlo,
    float* __restrict__ o)
{
    extern __shared__ char smbase[];
    __nv_bfloat16* Qhi = (__nv_bfloat16*)smbase;
    __nv_bfloat16* Qlo = Qhi + SZ_QK;
    __nv_bfloat16* KhiB = Qlo + SZ_QK;     // [2][SZ_QK]
    __nv_bfloat16* KloB = KhiB + 2 * SZ_QK;
    __nv_bfloat16* VhiB = KloB + 2 * SZ_QK;
    __nv_bfloat16* VloB = VhiB + 2 * SZ_QK;
    float* Ss = (float*)(VloB + 2 * SZ_QK);       // 64 x 68 fp32
    __nv_bfloat16* Ph = (__nv_bfloat16*)(Ss + 64 * 68);
    __nv_bfloat16* Pl = Ph + 64 * P_PITCH;
    float* mrow = (float*)(Pl + 64 * P_PITCH);
    float* lrow = mrow + 64;
    float* srow = lrow + 64;

    unsigned* Qhi32 = (unsigned*)Qhi;
    unsigned* Qlo32 = (unsigned*)Qlo;
    unsigned* Ph32 = (unsigned*)Ph;
    unsigned* Pl32 = (unsigned*)Pl;

    const int qb = gridDim.x - 1 - blockIdx.x;   // heavy blocks first
    const int h = blockIdx.y;
    const int b = blockIdx.z;
    const int tid = threadIdx.x;
    const int lane = tid & 31;
    const int qr = lane >> 2;
    const int qc = lane & 3;
    const int w = tid >> 5;
    const int wm = w >> 2;
    const int wn = w & 3;

    const size_t headoff = (size_t)h * HD;
    const float* qbase = q + ((size_t)b * Tv + (size_t)qb * 64) * Cv + headoff;

    // per-thread copy coordinates (16B granules): 4 chunks over 64x128 halves
    const int crow[4] = { (tid + 0) >> 4, (tid + 256) >> 4,
                          (tid + 512) >> 4, (tid + 768) >> 4 };
    const int cch[4] = { (tid + 0) & 15, (tid + 256) & 15,
                         (tid + 512) & 15, (tid + 768) & 15 };

    // ---- prologue: cp.async KV tile 0 into buffer 0 ----
    {
        const size_t tbase = ((size_t)b * Tv) * Cv + headoff;
#pragma unroll
        for (int it = 0; it < 4; ++it) {
            int row = crow[it];
            int ch = cch[it];
            size_t goff = (size_t)row * Cv + ch * 8;
            unsigned ksm = smem_u32(KhiB) + (row * 68 + ch * 4) * 4;
            cp_async16(ksm, khi + tbase + goff);
            cp_async16(ksm + 2 * SZ_QK * 2 * 1, klo + tbase + goff);  // KloB = KhiB + 2*SZ_QK halves
            unsigned vsm = smem_u32(VhiB) + (row * QK_PITCH + ch * 8) * 2;
            cp_async16(vsm, vhi + tbase + goff);
            cp_async16(vsm + 2 * SZ_QK * 2 * 1, vlo + tbase + goff);  // VloB offset
        }
        asm volatile("cp.async.commit_group;");
    }

    // ---- load + split Q (once per block) ----
#pragma unroll
    for (int it = 0; it < 8; ++it) {
        int idx = tid + it * 256;
        int row = idx >> 5;
        int c4 = (idx & 31) << 2;
        float4 qv = *(const float4*)(qbase + (size_t)row * Cv + c4);
        unsigned h0, l0, h1, l1;
        splitpack_bf16(qv.x, qv.y, h0, l0);
        splitpack_bf16(qv.z, qv.w, h1, l1);
        int base = row * 68 + (c4 >> 1);
        Qhi32[base] = h0; Qhi32[base + 1] = h1;
        Qlo32[base] = l0; Qlo32[base + 1] = l1;
    }
    if (tid < 64) {
        mrow[tid] = -3.0e38f;
        lrow[tid] = 0.f;
    }

    float oacc[2][4][4];
#pragma unroll
    for (int mt = 0; mt < 2; ++mt)
#pragma unroll
        for (int nt = 0; nt < 4; ++nt)
#pragma unroll
            for (int i = 0; i < 4; ++i) oacc[mt][nt][i] = 0.f;

    const float sscale = 0.08838834764831845f;  // 1/sqrt(128)

    for (int jt = 0; jt <= qb; ++jt) {
        const int cur = jt & 1;
        __syncthreads();  // prior iter's reads of buf[cur^1] complete

        const bool hn = (jt + 1 <= qb);
        if (hn) {
            const int alt = cur ^ 1;
            const size_t tbase = ((size_t)b * Tv + (size_t)(jt + 1) * 64) * Cv + headoff;
#pragma unroll
            for (int it = 0; it < 4; ++it) {
                int row = crow[it];
                int ch = cch[it];
                size_t goff = (size_t)row * Cv + ch * 8;
                unsigned ksm = smem_u32(KhiB + alt * SZ_QK) + (row * 68 + ch * 4) * 4;
                cp_async16(ksm, khi + tbase + goff);
                cp_async16(smem_u32(KloB + alt * SZ_QK) + (row * 68 + ch * 4) * 4,
                           klo + tbase + goff);
                cp_async16(smem_u32(VhiB + alt * SZ_QK) + (row * QK_PITCH + ch * 8) * 2,
                           vhi + tbase + goff);
                cp_async16(smem_u32(VloB + alt * SZ_QK) + (row * QK_PITCH + ch * 8) * 2,
                           vlo + tbase + goff);
            }
            asm volatile("cp.async.commit_group;");
            asm volatile("cp.async.wait_group 1;");
        } else {
            asm volatile("cp.async.wait_group 0;");
        }
        __syncthreads();  // tile jt visible to all threads

        unsigned* Khi32 = (unsigned*)(KhiB + cur * SZ_QK);
        unsigned* Klo32 = (unsigned*)(KloB + cur * SZ_QK);
        __nv_bfloat16* Vhi = VhiB + cur * SZ_QK;
        __nv_bfloat16* Vlo = VloB + cur * SZ_QK;

        // ---- S = Q K^T, bf16 3-pass over k=128 (8 k16 steps) ----
        float sacc[2][2][4];
#pragma unroll
        for (int mt = 0; mt < 2; ++mt)
#pragma unroll
            for (int nt = 0; nt < 2; ++nt)
#pragma unroll
                for (int i = 0; i < 4; ++i) sacc[mt][nt][i] = 0.f;

#pragma unroll
        for (int t = 0; t < 8; ++t) {
            unsigned qh[2][4], ql[2][4];
#pragma unroll
            for (int mt = 0; mt < 2; ++mt) {
                int r0 = wm * 32 + mt * 16;
                int b0 = (r0 + qr) * 68 + t * 8 + qc;
                int b1 = (r0 + 8 + qr) * 68 + t * 8 + qc;
                qh[mt][0] = Qhi32[b0]; qh[mt][1] = Qhi32[b1];
                qh[mt][2] = Qhi32[b0 + 4]; qh[mt][3] = Qhi32[b1 + 4];
                ql[mt][0] = Qlo32[b0]; ql[mt][1] = Qlo32[b1];
                ql[mt][2] = Qlo32[b0 + 4]; ql[mt][3] = Qlo32[b1 + 4];
            }
            unsigned kh[2][2], kl[2][2];
#pragma unroll
            for (int nt = 0; nt < 2; ++nt) {
                int n0 = wn * 16 + nt * 8;
                int bb = (n0 + qr) * 68 + t * 8 + qc;
                kh[nt][0] = Khi32[bb]; kh[nt][1] = Khi32[bb + 4];
                kl[nt][0] = Klo32[bb]; kl[nt][1] = Klo32[bb + 4];
            }
#pragma unroll
            for (int mt = 0; mt < 2; ++mt)
#pragma unroll
                for (int nt = 0; nt < 2; ++nt) {
                    mma_bf16(sacc[mt][nt], qh[mt], kh[nt]);
                    mma_bf16(sacc[mt][nt], qh[mt], kl[nt]);
                    mma_bf16(sacc[mt][nt], ql[mt], kh[nt]);
                }
        }

        // ---- scale + causal mask + stage S (fp32) ----
#pragma unroll
        for (int mt = 0; mt < 2; ++mt) {
#pragma unroll
            for (int nt = 0; nt < 2; ++nt) {
                int row = wm * 32 + mt * 16 + qr;
                int col = wn * 16 + nt * 8 + 2 * qc;
                int rowg = qb * 64 + row;
                int colg = jt * 64 + col;
                float s0 = sacc[mt][nt][0] * sscale;
                float s1 = sacc[mt][nt][1] * sscale;
                float s2 = sacc[mt][nt][2] * sscale;
                float s3 = sacc[mt][nt][3] * sscale;
                if (colg > rowg) s0 = -1e30f;
                if (colg + 1 > rowg) s1 = -1e30f;
                if (colg > rowg + 8) s2 = -1e30f;
                if (colg + 1 > rowg + 8) s3 = -1e30f;
                *(float2*)&Ss[row * 68 + col] = make_float2(s0, s1);
                *(float2*)&Ss[(row + 8) * 68 + col] = make_float2(s2, s3);
            }
        }
        __syncthreads();

        // ---- online softmax, 4 threads per row; P split to bf16 hi/lo ----
        {
            int r = tid >> 2;
            int part = tid & 3;
            float* srP = &Ss[r * 68 + part * 16];
            __nv_bfloat16* php = &Ph[r * P_PITCH + part * 16];
            __nv_bfloat16* plp = &Pl[r * P_PITCH + part * 16];
            float mx = -3.0e38f;
#pragma unroll
            for (int j = 0; j < 16; ++j) mx = fmaxf(mx, srP[j]);
            mx = fmaxf(mx, __shfl_xor_sync(0xffffffffu, mx, 1));
            mx = fmaxf(mx, __shfl_xor_sync(0xffffffffu, mx, 2));
            float mo = mrow[r];
            float mn = fmaxf(mo, mx);
            float ls = 0.f;
#pragma unroll
            for (int j = 0; j < 16; ++j) {
                float p = __expf(srP[j] - mn);
                __nv_bfloat16 ph, pl;
                split_bf16(p, ph, pl);
                php[j] = ph;
                plp[j] = pl;
                ls += p;
            }
            ls += __shfl_xor_sync(0xffffffffu, ls, 1);
            ls += __shfl_xor_sync(0xffffffffu, ls, 2);
            if (part == 0) {
                float sc = __expf(mo - mn);
                lrow[r] = lrow[r] * sc + ls;
                mrow[r] = mn;
                srow[r] = sc;
            }
        }
        __syncthreads();

        // ---- rescale O, then O += P V (bf16 3-pass over k=64) ----
#pragma unroll
        for (int mt = 0; mt < 2; ++mt) {
            int r0 = wm * 32 + mt * 16;
            float sc0 = srow[r0 + qr];
            float sc1 = srow[r0 + 8 + qr];
#pragma unroll
            for (int nt = 0; nt < 4; ++nt) {
                oacc[mt][nt][0] *= sc0;
                oacc[mt][nt][1] *= sc0;
                oacc[mt][nt][2] *= sc1;
                oacc[mt][nt][3] *= sc1;
            }
        }

#pragma unroll
        for (int t = 0; t < 4; ++t) {
            unsigned ph[2][4], pl[2][4];
#pragma unroll
            for (int mt = 0; mt < 2; ++mt) {
                int r0 = wm * 32 + mt * 16;
                int b0 = (r0 + qr) * 36 + t * 8 + qc;
                int b1 = (r0 + 8 + qr) * 36 + t * 8 + qc;
                ph[mt][0] = Ph32[b0]; ph[mt][1] = Ph32[b1];
                ph[mt][2] = Ph32[b0 + 4]; ph[mt][3] = Ph32[b1 + 4];
                pl[mt][0] = Pl32[b0]; pl[mt][1] = Pl32[b1];
                pl[mt][2] = Pl32[b0 + 4]; pl[mt][3] = Pl32[b1 + 4];
            }
            int vrow = 16 * t + (lane & 15);
#pragma unroll
            for (int nt = 0; nt < 4; ++nt) {
                int n0 = wn * 32 + nt * 8;
                unsigned vh[2], vl[2];
                ldmatrix_x2_trans(vh[0], vh[1],
                                  smem_u32(&Vhi[vrow * QK_PITCH + n0]));
                ldmatrix_x2_trans(vl[0], vl[1],
                                  smem_u32(&Vlo[vrow * QK_PITCH + n0]));
#pragma unroll
                for (int mt = 0; mt < 2; ++mt) {
                    mma_bf16(oacc[mt][nt], ph[mt], vh);
                    mma_bf16(oacc[mt][nt], ph[mt], vl);
                    mma_bf16(oacc[mt][nt], pl[mt], vh);
                }
            }
        }
    }

    // ---- epilogue: normalize and store ----
    float* obase = o + ((size_t)b * Tv + (size_t)qb * 64) * Cv + headoff;
#pragma unroll
    for (int mt = 0; mt < 2; ++mt) {
        int r0 = wm * 32 + mt * 16;
        float inv0 = 1.f / lrow[r0 + qr];
        float inv1 = 1.f / lrow[r0 + 8 + qr];
#pragma unroll
        for (int nt = 0; nt < 4; ++nt) {
            int col = wn * 32 + nt * 8 + 2 * qc;
            *(float2*)(obase + (size_t)(r0 + qr) * Cv + col) =
                make_float2(oacc[mt][nt][0] * inv0, oacc[mt][nt][1] * inv0);
            *(float2*)(obase + (size_t)(r0 + 8 + qr) * Cv + col) =
                make_float2(oacc[mt][nt][2] * inv1, oacc[mt][nt][3] * inv1);
        }
    }
}

// ---------------------------------------------------------------------------
// LayerNorm over last dim (2048) per row.
// ---------------------------------------------------------------------------
__global__ __launch_bounds__(256) void layernorm_kernel(
    const float* __restrict__ in, const float* __restrict__ gamma,
    const float* __restrict__ beta, float* __restrict__ out)
{
    __shared__ float ws[8], ws2[8];
    const int row = blockIdx.x;
    const int t = threadIdx.x;
    const float* p = in + (size_t)row * Cv;

    float4 x0 = *(const float4*)(p + t * 8);
    float4 x1 = *(const float4*)(p + t * 8 + 4);
    float s = x0.x + x0.y + x0.z + x0.w + x1.x + x1.y + x1.z + x1.w;
    float s2 = x0.x * x0.x + x0.y * x0.y + x0.z * x0.z + x0.w * x0.w +
               x1.x * x1.x + x1.y * x1.y + x1.z * x1.z + x1.w * x1.w;

#pragma unroll
    for (int off = 16; off > 0; off >>= 1) {
        s += __shfl_xor_sync(0xffffffffu, s, off);
        s2 += __shfl_xor_sync(0xffffffffu, s2, off);
    }
    const int wid = t >> 5, lid = t & 31;
    if (lid == 0) { ws[wid] = s; ws2[wid] = s2; }
    __syncthreads();
    if (t == 0) {
        float a = 0.f, a2 = 0.f;
#pragma unroll
        for (int i = 0; i < 8; ++i) { a += ws[i]; a2 += ws2[i]; }
        ws[0] = a; ws2[0] = a2;
    }
    __syncthreads();
    const float mu = ws[0] / (float)Cv;
    const float var = ws2[0] / (float)Cv - mu * mu;
    const float inv = rsqrtf(var + 1e-5f);

    float4 g0 = *(const float4*)(gamma + t * 8);
    float4 g1 = *(const float4*)(gamma + t * 8 + 4);
    float4 b0 = *(const float4*)(beta + t * 8);
    float4 b1 = *(const float4*)(beta + t * 8 + 4);
    float4 o0, o1;
    o0.x = (x0.x - mu) * inv * g0.x + b0.x;
    o0.y = (x0.y - mu) * inv * g0.y + b0.y;
    o0.z = (x0.z - mu) * inv * g0.z + b0.z;
    o0.w = (x0.w - mu) * inv * g0.w + b0.w;
    o1.x = (x1.x - mu) * inv * g1.x + b1.x;
    o1.y = (x1.y - mu) * inv * g1.y + b1.y;
    o1.z = (x1.z - mu) * inv * g1.z + b1.z;
    o1.w = (x1.w - mu) * inv * g1.w + b1.w;
    *(float4*)(out + (size_t)row * Cv + t * 8) = o0;
    *(float4*)(out + (size_t)row * Cv + t * 8 + 4) = o1;
}

// ---------------------------------------------------------------------------
extern "C" void kernel_launch(void* const* d_in, const int* in_sizes, int n_in,
                              void* d_out, int out_size)
{
    const float* x  = (const float*)d_in[0];
    const float* Wq = (const float*)d_in[1];
    const float* Wk = (const float*)d_in[2];
    const float* Wv = (const float*)d_in[3];
    const float* Wo = (const float*)d_in[4];
    const float* gm = (const float*)d_in[5];
    const float* bt = (const float*)d_in[6];
    float* out = (float*)d_out;

    float *qp, *kp, *vp, *ap, *pp;
    __nv_bfloat16 *khp, *klp, *vhp, *vlp;
    cudaGetSymbolAddress((void**)&qp, g_q);
    cudaGetSymbolAddress((void**)&kp, g_k);
    cudaGetSymbolAddress((void**)&vp, g_v);
    cudaGetSymbolAddress((void**)&ap, g_attn);
    cudaGetSymbolAddress((void**)&pp, g_proj);
    cudaGetSymbolAddress((void**)&khp, g_khi);
    cudaGetSymbolAddress((void**)&klp, g_klo);
    cudaGetSymbolAddress((void**)&vhp, g_vhi);
    cudaGetSymbolAddress((void**)&vlp, g_vlo);

    cudaFuncSetAttribute(flash_attn_bf16,
                         cudaFuncAttributeMaxDynamicSharedMemorySize,
                         FA_SMEM_BYTES);

    dim3 qkvgrid(Cv / 128, ROWS / 128, 3);  // (16, 32, 3)
    tf32_gemm_qkv<<<qkvgrid, 256>>>(x, Wq, Wk, Wv, qp, kp, vp, ROWS, Cv, Cv);

    rope_split_kernel<<<Bv * Tv * Hv, 64>>>(qp, kp, vp, khp, klp, vhp, vlp);

    dim3 agrid(Tv / 64, Hv, Bv);  // (32, 16, 2)
    flash_attn_bf16<<<agrid, 256, FA_SMEM_BYTES>>>(qp, khp, klp, vhp, vlp, ap);

    dim3 ggrid(Cv / 128, ROWS / 128);  // (16, 32)
    tf32_gemm_nt<<<ggrid, 256>>>(ap, Wo, pp, ROWS, Cv, Cv);
    layernorm_kernel<<<ROWS, 256>>>(pp, gm, bt, out);
}

// round 16
// speedup vs baseline: 1.3676x; 1.0125x over previous
#include <cuda_runtime.h>
#include <cuda_bf16.h>
#include <cstdint>
#include <math.h>

static constexpr int Bv = 2;
static constexpr int Tv = 2048;
static constexpr int Cv = 2048;
static constexpr int Hv = 16;
static constexpr int HD = 128;
static constexpr int ROWS = Bv * Tv;  // 4096

__device__ float g_q[(size_t)Bv * Tv * Cv];
__device__ float g_k[(size_t)Bv * Tv * Cv];
__device__ float g_v[(size_t)Bv * Tv * Cv];
__device__ float g_attn[(size_t)Bv * Tv * Cv];
__device__ float g_proj[(size_t)Bv * Tv * Cv];
// tf32-rounded copies of x and the 4 weights
__device__ float g_xr[(size_t)ROWS * Cv];
__device__ float g_wr[(size_t)4 * Cv * Cv];
// pre-split bf16 hi/lo of (roped) K and V
__device__ __nv_bfloat16 g_khi[(size_t)Bv * Tv * Cv];
__device__ __nv_bfloat16 g_klo[(size_t)Bv * Tv * Cv];
__device__ __nv_bfloat16 g_vhi[(size_t)Bv * Tv * Cv];
__device__ __nv_bfloat16 g_vlo[(size_t)Bv * Tv * Cv];

// ---------------------------------------------------------------------------
// helpers
// ---------------------------------------------------------------------------
__device__ __forceinline__ unsigned smem_u32(const void* p) {
    return (unsigned)__cvta_generic_to_shared(p);
}

__device__ __forceinline__ unsigned f2tf32(float x) {
    unsigned r;
    asm("cvt.rna.tf32.f32 %0, %1;" : "=r"(r) : "f"(x));
    return r;
}

__device__ __forceinline__ void mma_tf32(float* d, const unsigned* a, const unsigned* b) {
    asm volatile(
        "mma.sync.aligned.m16n8k8.row.col.f32.tf32.tf32.f32 "
        "{%0,%1,%2,%3}, {%4,%5,%6,%7}, {%8,%9}, {%0,%1,%2,%3};"
        : "+f"(d[0]), "+f"(d[1]), "+f"(d[2]), "+f"(d[3])
        : "r"(a[0]), "r"(a[1]), "r"(a[2]), "r"(a[3]), "r"(b[0]), "r"(b[1]));
}

__device__ __forceinline__ void mma_bf16(float* d, const unsigned* a, const unsigned* b) {
    asm volatile(
        "mma.sync.aligned.m16n8k16.row.col.f32.bf16.bf16.f32 "
        "{%0,%1,%2,%3}, {%4,%5,%6,%7}, {%8,%9}, {%0,%1,%2,%3};"
        : "+f"(d[0]), "+f"(d[1]), "+f"(d[2]), "+f"(d[3])
        : "r"(a[0]), "r"(a[1]), "r"(a[2]), "r"(a[3]), "r"(b[0]), "r"(b[1]));
}

__device__ __forceinline__ void ldmatrix_x2_trans(unsigned& r0, unsigned& r1, unsigned addr) {
    asm volatile("ldmatrix.sync.aligned.m8n8.x2.trans.shared.b16 {%0,%1}, [%2];"
                 : "=r"(r0), "=r"(r1) : "r"(addr));
}

__device__ __forceinline__ void cp_async16(unsigned smem_addr, const void* gptr) {
    asm volatile("cp.async.cg.shared.global [%0], [%1], 16;"
                 :: "r"(smem_addr), "l"(gptr));
}

__device__ __forceinline__ void split_bf16(float x, __nv_bfloat16& h, __nv_bfloat16& l) {
    h = __float2bfloat16_rn(x);
    l = __float2bfloat16_rn(x - __bfloat162float(h));
}

__device__ __forceinline__ void splitpack_bf16(float v0, float v1,
                                               unsigned& hi, unsigned& lo) {
    __nv_bfloat16 h0, l0, h1, l1;
    split_bf16(v0, h0, l0);
    split_bf16(v1, h1, l1);
    hi = (unsigned)__bfloat16_as_ushort(h0) | ((unsigned)__bfloat16_as_ushort(h1) << 16);
    lo = (unsigned)__bfloat16_as_ushort(l0) | ((unsigned)__bfloat16_as_ushort(l1) << 16);
}

// ---------------------------------------------------------------------------
// Elementwise tf32 rounding pre-pass: dst[i] = rna_tf32(src[i]).
// ---------------------------------------------------------------------------
__global__ __launch_bounds__(256) void round_tf32_kernel(
    const float* __restrict__ src, float* __restrict__ dst, int n4)
{
    int i = blockIdx.x * 256 + threadIdx.x;
    if (i < n4) {
        float4 v = ((const float4*)src)[i];
        v.x = __uint_as_float(f2tf32(v.x));
        v.y = __uint_as_float(f2tf32(v.y));
        v.z = __uint_as_float(f2tf32(v.z));
        v.w = __uint_as_float(f2tf32(v.w));
        ((float4*)dst)[i] = v;
    }
}

__global__ __launch_bounds__(256) void round_tf32_w_kernel(
    const float* __restrict__ w0, const float* __restrict__ w1,
    const float* __restrict__ w2, const float* __restrict__ w3,
    float* __restrict__ dst, int n4)
{
    const float* src = (blockIdx.z == 0) ? w0 : (blockIdx.z == 1) ? w1
                     : (blockIdx.z == 2) ? w2 : w3;
    float* d = dst + (size_t)blockIdx.z * Cv * Cv;
    int i = blockIdx.x * 256 + threadIdx.x;
    if (i < n4) {
        float4 v = ((const float4*)src)[i];
        v.x = __uint_as_float(f2tf32(v.x));
        v.y = __uint_as_float(f2tf32(v.y));
        v.z = __uint_as_float(f2tf32(v.z));
        v.w = __uint_as_float(f2tf32(v.w));
        ((float4*)d)[i] = v;
    }
}

// ---------------------------------------------------------------------------
// TF32 tensor-core GEMM (R12 structure; inputs pre-rounded -> pure copy fill):
// C[m][n] = sum_k A[m*K+k] * B[n*K+k]  (NT, K-major), static smem, 2 syncs.
// ---------------------------------------------------------------------------
__device__ __forceinline__ void tf32_gemm_body(
    const float* __restrict__ A, const float* __restrict__ B,
    float* __restrict__ C, int M, int N, int K)
{
    __shared__ __align__(16) float As[128][36];
    __shared__ __align__(16) float Bs[128][36];

    const int tid = threadIdx.x;
    const int bm = blockIdx.y * 128;
    const int bn = blockIdx.x * 128;

    const int w = tid >> 5;
    const int wr = w >> 2;
    const int wc = w & 3;
    const int lane = tid & 31;
    const int qr = lane >> 2;
    const int qc = lane & 3;

    float4 pa[4], pb[4];
#pragma unroll
    for (int it = 0; it < 4; ++it) {
        int lin = tid + it * 256;
        int row = lin >> 3;
        int c4 = (lin & 7) << 2;
        pa[it] = *(const float4*)(A + (size_t)(bm + row) * K + c4);
        pb[it] = *(const float4*)(B + (size_t)(bn + row) * K + c4);
    }

    float acc[4][4][4];
#pragma unroll
    for (int mt = 0; mt < 4; ++mt)
#pragma unroll
        for (int nt = 0; nt < 4; ++nt)
#pragma unroll
            for (int i = 0; i < 4; ++i) acc[mt][nt][i] = 0.f;

    for (int kt = 0; kt < K; kt += 32) {
        __syncthreads();
#pragma unroll
        for (int it = 0; it < 4; ++it) {
            int lin = tid + it * 256;
            int row = lin >> 3;
            int c4 = (lin & 7) << 2;
            *(float4*)&As[row][c4] = pa[it];
            *(float4*)&Bs[row][c4] = pb[it];
        }
        __syncthreads();

        if (kt + 32 < K) {
#pragma unroll
            for (int it = 0; it < 4; ++it) {
                int lin = tid + it * 256;
                int row = lin >> 3;
                int c4 = (lin & 7) << 2;
                pa[it] = *(const float4*)(A + (size_t)(bm + row) * K + kt + 32 + c4);
                pb[it] = *(const float4*)(B + (size_t)(bn + row) * K + kt + 32 + c4);
            }
        }

#pragma unroll
        for (int k8 = 0; k8 < 4; ++k8) {
            const int k0 = k8 * 8;
            unsigned afr[4][4];
#pragma unroll
            for (int mt = 0; mt < 4; ++mt) {
                int r0 = wr * 64 + mt * 16 + qr;
                afr[mt][0] = __float_as_uint(As[r0][k0 + qc]);
                afr[mt][1] = __float_as_uint(As[r0 + 8][k0 + qc]);
                afr[mt][2] = __float_as_uint(As[r0][k0 + qc + 4]);
                afr[mt][3] = __float_as_uint(As[r0 + 8][k0 + qc + 4]);
            }
            unsigned bfr[4][2];
#pragma unroll
            for (int nt = 0; nt < 4; ++nt) {
                int n0 = wc * 32 + nt * 8 + qr;
                bfr[nt][0] = __float_as_uint(Bs[n0][k0 + qc]);
                bfr[nt][1] = __float_as_uint(Bs[n0][k0 + qc + 4]);
            }
#pragma unroll
            for (int mt = 0; mt < 4; ++mt)
#pragma unroll
                for (int nt = 0; nt < 4; ++nt)
                    mma_tf32(acc[mt][nt], afr[mt], bfr[nt]);
        }
    }

#pragma unroll
    for (int mt = 0; mt < 4; ++mt) {
#pragma unroll
        for (int nt = 0; nt < 4; ++nt) {
            int row = bm + wr * 64 + mt * 16 + qr;
            int col = bn + wc * 32 + nt * 8 + 2 * qc;
            *(float2*)(C + (size_t)row * N + col) =
                make_float2(acc[mt][nt][0], acc[mt][nt][1]);
            *(float2*)(C + (size_t)(row + 8) * N + col) =
                make_float2(acc[mt][nt][2], acc[mt][nt][3]);
        }
    }
}

__global__ __launch_bounds__(256) void tf32_gemm_nt(
    const float* __restrict__ A, const float* __restrict__ B,
    float* __restrict__ C, int M, int N, int K)
{
    tf32_gemm_body(A, B, C, M, N, K);
}

__global__ __launch_bounds__(256) void tf32_gemm_qkv(
    const float* __restrict__ x, const float* __restrict__ wr,
    float* __restrict__ q, float* __restrict__ k, float* __restrict__ v,
    int M, int N, int K)
{
    const float* B = wr + (size_t)blockIdx.z * Cv * Cv;
    float* C = (blockIdx.z == 0) ? q : (blockIdx.z == 1) ? k : v;
    tf32_gemm_body(x, B, C, M, N, K);
}

// ---------------------------------------------------------------------------
// RoPE on q (in-place fp32) and k (-> bf16 hi/lo); V convert (-> bf16 hi/lo).
// ---------------------------------------------------------------------------
__global__ void rope_split_kernel(
    float* __restrict__ q, const float* __restrict__ k, const float* __restrict__ v,
    __nv_bfloat16* __restrict__ khi, __nv_bfloat16* __restrict__ klo,
    __nv_bfloat16* __restrict__ vhi, __nv_bfloat16* __restrict__ vlo)
{
    const int idx = blockIdx.x;
    const int h = idx % Hv;
    const int t = (idx / Hv) % Tv;
    const int b = idx / (Hv * Tv);
    const int d = threadIdx.x;  // 0..63

    const float e = (2.0f * (float)d) / (float)HD;
    const float inv_freq = 1.0f / powf(10000.0f, e);
    const float ang = (float)t * inv_freq;
    float s, c;
    sincosf(ang, &s, &c);

    const size_t base = ((size_t)(b * Tv + t)) * Cv + (size_t)h * HD;

    float q0 = q[base + d], q1 = q[base + d + 64];
    q[base + d]      = q0 * c - q1 * s;
    q[base + d + 64] = q1 * c + q0 * s;

    float k0 = k[base + d], k1 = k[base + d + 64];
    float kr0 = k0 * c - k1 * s;
    float kr1 = k1 * c + k0 * s;
    __nv_bfloat16 hh, ll;
    split_bf16(kr0, hh, ll);
    khi[base + d] = hh; klo[base + d] = ll;
    split_bf16(kr1, hh, ll);
    khi[base + d + 64] = hh; klo[base + d + 64] = ll;

    float v0 = v[base + d], v1 = v[base + d + 64];
    split_bf16(v0, hh, ll);
    vhi[base + d] = hh; vlo[base + d] = ll;
    split_bf16(v1, hh, ll);
    vhi[base + d + 64] = hh; vlo[base + d + 64] = ll;
}

// ---------------------------------------------------------------------------
// Causal flash attention (R15 version + tf32-rounded output for Wo GEMM).
// bf16 m16n8k16 hi/lo, 64-row q-tiles, cp.async KV double buffer, heavy-first.
// ---------------------------------------------------------------------------
static constexpr int QK_PITCH = 136;  // halves per row (b32 pitch 68)
static constexpr int P_PITCH = 72;    // halves per row (b32 pitch 36)
static constexpr int SZ_QK = 64 * QK_PITCH;   // halves per tile buffer
static constexpr int FA_SMEM_BYTES =
    2 * SZ_QK * 2 + 8 * SZ_QK * 2 + 64 * 68 * 4 +
    2 * 64 * P_PITCH * 2 + 3 * 64 * 4;  // 210688

__global__ __launch_bounds__(256) void flash_attn_bf16(
    const float* __restrict__ q,
    const __nv_bfloat16* __restrict__ khi, const __nv_bfloat16* __restrict__ klo,
    const __nv_bfloat16* __restrict__ vhi, const __nv_bfloat16* __restrict__ vlo,
    float* __restrict__ o)
{
    extern __shared__ char smbase[];
    __nv_bfloat16* Qhi = (__nv_bfloat16*)smbase;
    __nv_bfloat16* Qlo = Qhi + SZ_QK;
    __nv_bfloat16* KhiB = Qlo + SZ_QK;     // [2][SZ_QK]
    __nv_bfloat16* KloB = KhiB + 2 * SZ_QK;
    __nv_bfloat16* VhiB = KloB + 2 * SZ_QK;
    __nv_bfloat16* VloB = VhiB + 2 * SZ_QK;
    float* Ss = (float*)(VloB + 2 * SZ_QK);       // 64 x 68 fp32
    __nv_bfloat16* Ph = (__nv_bfloat16*)(Ss + 64 * 68);
    __nv_bfloat16* Pl = Ph + 64 * P_PITCH;
    float* mrow = (float*)(Pl + 64 * P_PITCH);
    float* lrow = mrow + 64;
    float* srow = lrow + 64;

    unsigned* Qhi32 = (unsigned*)Qhi;
    unsigned* Qlo32 = (unsigned*)Qlo;
    unsigned* Ph32 = (unsigned*)Ph;
    unsigned* Pl32 = (unsigned*)Pl;

    const int qb = gridDim.x - 1 - blockIdx.x;   // heavy blocks first
    const int h = blockIdx.y;
    const int b = blockIdx.z;
    const int tid = threadIdx.x;
    const int lane = tid & 31;
    const int qr = lane >> 2;
    const int qc = lane & 3;
    const int w = tid >> 5;
    const int wm = w >> 2;
    const int wn = w & 3;

    const size_t headoff = (size_t)h * HD;
    const float* qbase = q + ((size_t)b * Tv + (size_t)qb * 64) * Cv + headoff;

    const int crow[4] = { (tid + 0) >> 4, (tid + 256) >> 4,
                          (tid + 512) >> 4, (tid + 768) >> 4 };
    const int cch[4] = { (tid + 0) & 15, (tid + 256) & 15,
                         (tid + 512) & 15, (tid + 768) & 15 };

    // ---- prologue: cp.async KV tile 0 into buffer 0 ----
    {
        const size_t tbase = ((size_t)b * Tv) * Cv + headoff;
#pragma unroll
        for (int it = 0; it < 4; ++it) {
            int row = crow[it];
            int ch = cch[it];
            size_t goff = (size_t)row * Cv + ch * 8;
            cp_async16(smem_u32(KhiB) + (row * 68 + ch * 4) * 4, khi + tbase + goff);
            cp_async16(smem_u32(KloB) + (row * 68 + ch * 4) * 4, klo + tbase + goff);
            cp_async16(smem_u32(VhiB) + (row * QK_PITCH + ch * 8) * 2, vhi + tbase + goff);
            cp_async16(smem_u32(VloB) + (row * QK_PITCH + ch * 8) * 2, vlo + tbase + goff);
        }
        asm volatile("cp.async.commit_group;");
    }

    // ---- load + split Q (once per block) ----
#pragma unroll
    for (int it = 0; it < 8; ++it) {
        int idx = tid + it * 256;
        int row = idx >> 5;
        int c4 = (idx & 31) << 2;
        float4 qv = *(const float4*)(qbase + (size_t)row * Cv + c4);
        unsigned h0, l0, h1, l1;
        splitpack_bf16(qv.x, qv.y, h0, l0);
        splitpack_bf16(qv.z, qv.w, h1, l1);
        int base = row * 68 + (c4 >> 1);
        Qhi32[base] = h0; Qhi32[base + 1] = h1;
        Qlo32[base] = l0; Qlo32[base + 1] = l1;
    }
    if (tid < 64) {
        mrow[tid] = -3.0e38f;
        lrow[tid] = 0.f;
    }

    float oacc[2][4][4];
#pragma unroll
    for (int mt = 0; mt < 2; ++mt)
#pragma unroll
        for (int nt = 0; nt < 4; ++nt)
#pragma unroll
            for (int i = 0; i < 4; ++i) oacc[mt][nt][i] = 0.f;

    const float sscale = 0.08838834764831845f;  // 1/sqrt(128)

    for (int jt = 0; jt <= qb; ++jt) {
        const int cur = jt & 1;
        __syncthreads();  // prior iter's reads of buf[cur^1] complete

        const bool hn = (jt + 1 <= qb);
        if (hn) {
            const int alt = cur ^ 1;
            const size_t tbase = ((size_t)b * Tv + (size_t)(jt + 1) * 64) * Cv + headoff;
#pragma unroll
            for (int it = 0; it < 4; ++it) {
                int row = crow[it];
                int ch = cch[it];
                size_t goff = (size_t)row * Cv + ch * 8;
                cp_async16(smem_u32(KhiB + alt * SZ_QK) + (row * 68 + ch * 4) * 4,
                           khi + tbase + goff);
                cp_async16(smem_u32(KloB + alt * SZ_QK) + (row * 68 + ch * 4) * 4,
                           klo + tbase + goff);
                cp_async16(smem_u32(VhiB + alt * SZ_QK) + (row * QK_PITCH + ch * 8) * 2,
                           vhi + tbase + goff);
                cp_async16(smem_u32(VloB + alt * SZ_QK) + (row * QK_PITCH + ch * 8) * 2,
                           vlo + tbase + goff);
            }
            asm volatile("cp.async.commit_group;");
            asm volatile("cp.async.wait_group 1;");
        } else {
            asm volatile("cp.async.wait_group 0;");
        }
        __syncthreads();  // tile jt visible to all threads

        unsigned* Khi32 = (unsigned*)(KhiB + cur * SZ_QK);
        unsigned* Klo32 = (unsigned*)(KloB + cur * SZ_QK);
        __nv_bfloat16* Vhi = VhiB + cur * SZ_QK;
        __nv_bfloat16* Vlo = VloB + cur * SZ_QK;

        // ---- S = Q K^T, bf16 3-pass over k=128 (8 k16 steps) ----
        float sacc[2][2][4];
#pragma unroll
        for (int mt = 0; mt < 2; ++mt)
#pragma unroll
            for (int nt = 0; nt < 2; ++nt)
#pragma unroll
                for (int i = 0; i < 4; ++i) sacc[mt][nt][i] = 0.f;

#pragma unroll
        for (int t = 0; t < 8; ++t) {
            unsigned qh[2][4], ql[2][4];
#pragma unroll
            for (int mt = 0; mt < 2; ++mt) {
                int r0 = wm * 32 + mt * 16;
                int b0 = (r0 + qr) * 68 + t * 8 + qc;
                int b1 = (r0 + 8 + qr) * 68 + t * 8 + qc;
                qh[mt][0] = Qhi32[b0]; qh[mt][1] = Qhi32[b1];
                qh[mt][2] = Qhi32[b0 + 4]; qh[mt][3] = Qhi32[b1 + 4];
                ql[mt][0] = Qlo32[b0]; ql[mt][1] = Qlo32[b1];
                ql[mt][2] = Qlo32[b0 + 4]; ql[mt][3] = Qlo32[b1 + 4];
            }
            unsigned kh[2][2], kl[2][2];
#pragma unroll
            for (int nt = 0; nt < 2; ++nt) {
                int n0 = wn * 16 + nt * 8;
                int bb = (n0 + qr) * 68 + t * 8 + qc;
                kh[nt][0] = Khi32[bb]; kh[nt][1] = Khi32[bb + 4];
                kl[nt][0] = Klo32[bb]; kl[nt][1] = Klo32[bb + 4];
            }
#pragma unroll
            for (int mt = 0; mt < 2; ++mt)
#pragma unroll
                for (int nt = 0; nt < 2; ++nt) {
                    mma_bf16(sacc[mt][nt], qh[mt], kh[nt]);
                    mma_bf16(sacc[mt][nt], qh[mt], kl[nt]);
                    mma_bf16(sacc[mt][nt], ql[mt], kh[nt]);
                }
        }

        // ---- scale + causal mask + stage S (fp32) ----
#pragma unroll
        for (int mt = 0; mt < 2; ++mt) {
#pragma unroll
            for (int nt = 0; nt < 2; ++nt) {
                int row = wm * 32 + mt * 16 + qr;
                int col = wn * 16 + nt * 8 + 2 * qc;
                int rowg = qb * 64 + row;
                int colg = jt * 64 + col;
                float s0 = sacc[mt][nt][0] * sscale;
                float s1 = sacc[mt][nt][1] * sscale;
                float s2 = sacc[mt][nt][2] * sscale;
                float s3 = sacc[mt][nt][3] * sscale;
                if (colg > rowg) s0 = -1e30f;
                if (colg + 1 > rowg) s1 = -1e30f;
                if (colg > rowg + 8) s2 = -1e30f;
                if (colg + 1 > rowg + 8) s3 = -1e30f;
                *(float2*)&Ss[row * 68 + col] = make_float2(s0, s1);
                *(float2*)&Ss[(row + 8) * 68 + col] = make_float2(s2, s3);
            }
        }
        __syncthreads();

        // ---- online softmax, 4 threads per row; P split to bf16 hi/lo ----
        {
            int r = tid >> 2;
            int part = tid & 3;
            float* srP = &Ss[r * 68 + part * 16];
            __nv_bfloat16* php = &Ph[r * P_PITCH + part * 16];
            __nv_bfloat16* plp = &Pl[r * P_PITCH + part * 16];
            float mx = -3.0e38f;
#pragma unroll
            for (int j = 0; j < 16; ++j) mx = fmaxf(mx, srP[j]);
            mx = fmaxf(mx, __shfl_xor_sync(0xffffffffu, mx, 1));
            mx = fmaxf(mx, __shfl_xor_sync(0xffffffffu, mx, 2));
            float mo = mrow[r];
            float mn = fmaxf(mo, mx);
            float ls = 0.f;
#pragma unroll
            for (int j = 0; j < 16; ++j) {
                float p = __expf(srP[j] - mn);
                __nv_bfloat16 ph, pl;
                split_bf16(p, ph, pl);
                php[j] = ph;
                plp[j] = pl;
                ls += p;
            }
            ls += __shfl_xor_sync(0xffffffffu, ls, 1);
            ls += __shfl_xor_sync(0xffffffffu, ls, 2);
            if (part == 0) {
                float sc = __expf(mo - mn);
                lrow[r] = lrow[r] * sc + ls;
                mrow[r] = mn;
                srow[r] = sc;
            }
        }
        __syncthreads();

        // ---- rescale O, then O += P V (bf16 3-pass over k=64) ----
#pragma unroll
        for (int mt = 0; mt < 2; ++mt) {
            int r0 = wm * 32 + mt * 16;
            float sc0 = srow[r0 + qr];
            float sc1 = srow[r0 + 8 + qr];
#pragma unroll
            for (int nt = 0; nt < 4; ++nt) {
                oacc[mt][nt][0] *= sc0;
                oacc[mt][nt][1] *= sc0;
                oacc[mt][nt][2] *= sc1;
                oacc[mt][nt][3] *= sc1;
            }
        }

#pragma unroll
        for (int t = 0; t < 4; ++t) {
            unsigned ph[2][4], pl[2][4];
#pragma unroll
            for (int mt = 0; mt < 2; ++mt) {
                int r0 = wm * 32 + mt * 16;
                int b0 = (r0 + qr) * 36 + t * 8 + qc;
                int b1 = (r0 + 8 + qr) * 36 + t * 8 + qc;
                ph[mt][0] = Ph32[b0]; ph[mt][1] = Ph32[b1];
                ph[mt][2] = Ph32[b0 + 4]; ph[mt][3] = Ph32[b1 + 4];
                pl[mt][0] = Pl32[b0]; pl[mt][1] = Pl32[b1];
                pl[mt][2] = Pl32[b0 + 4]; pl[mt][3] = Pl32[b1 + 4];
            }
            int vrow = 16 * t + (lane & 15);
#pragma unroll
            for (int nt = 0; nt < 4; ++nt) {
                int n0 = wn * 32 + nt * 8;
                unsigned vh[2], vl[2];
                ldmatrix_x2_trans(vh[0], vh[1],
                                  smem_u32(&Vhi[vrow * QK_PITCH + n0]));
                ldmatrix_x2_trans(vl[0], vl[1],
                                  smem_u32(&Vlo[vrow * QK_PITCH + n0]));
#pragma unroll
                for (int mt = 0; mt < 2; ++mt) {
                    mma_bf16(oacc[mt][nt], ph[mt], vh);
                    mma_bf16(oacc[mt][nt], ph[mt], vl);
                    mma_bf16(oacc[mt][nt], pl[mt], vh);
                }
            }
        }
    }

    // ---- epilogue: normalize, round to tf32 (for Wo GEMM), and store ----
    float* obase = o + ((size_t)b * Tv + (size_t)qb * 64) * Cv + headoff;
#pragma unroll
    for (int mt = 0; mt < 2; ++mt) {
        int r0 = wm * 32 + mt * 16;
        float inv0 = 1.f / lrow[r0 + qr];
        float inv1 = 1.f / lrow[r0 + 8 + qr];
#pragma unroll
        for (int nt = 0; nt < 4; ++nt) {
            int col = wn * 32 + nt * 8 + 2 * qc;
            *(float2*)(obase + (size_t)(r0 + qr) * Cv + col) = make_float2(
                __uint_as_float(f2tf32(oacc[mt][nt][0] * inv0)),
                __uint_as_float(f2tf32(oacc[mt][nt][1] * inv0)));
            *(float2*)(obase + (size_t)(r0 + 8 + qr) * Cv + col) = make_float2(
                __uint_as_float(f2tf32(oacc[mt][nt][2] * inv1)),
                __uint_as_float(f2tf32(oacc[mt][nt][3] * inv1)));
        }
    }
}

// ---------------------------------------------------------------------------
// LayerNorm over last dim (2048) per row.
// ---------------------------------------------------------------------------
__global__ __launch_bounds__(256) void layernorm_kernel(
    const float* __restrict__ in, const float* __restrict__ gamma,
    const float* __restrict__ beta, float* __restrict__ out)
{
    __shared__ float ws[8], ws2[8];
    const int row = blockIdx.x;
    const int t = threadIdx.x;
    const float* p = in + (size_t)row * Cv;

    float4 x0 = *(const float4*)(p + t * 8);
    float4 x1 = *(const float4*)(p + t * 8 + 4);
    float s = x0.x + x0.y + x0.z + x0.w + x1.x + x1.y + x1.z + x1.w;
    float s2 = x0.x * x0.x + x0.y * x0.y + x0.z * x0.z + x0.w * x0.w +
               x1.x * x1.x + x1.y * x1.y + x1.z * x1.z + x1.w * x1.w;

#pragma unroll
    for (int off = 16; off > 0; off >>= 1) {
        s += __shfl_xor_sync(0xffffffffu, s, off);
        s2 += __shfl_xor_sync(0xffffffffu, s2, off);
    }
    const int wid = t >> 5, lid = t & 31;
    if (lid == 0) { ws[wid] = s; ws2[wid] = s2; }
    __syncthreads();
    if (t == 0) {
        float a = 0.f, a2 = 0.f;
#pragma unroll
        for (int i = 0; i < 8; ++i) { a += ws[i]; a2 += ws2[i]; }
        ws[0] = a; ws2[0] = a2;
    }
    __syncthreads();
    const float mu = ws[0] / (float)Cv;
    const float var = ws2[0] / (float)Cv - mu * mu;
    const float inv = rsqrtf(var + 1e-5f);

    float4 g0 = *(const float4*)(gamma + t * 8);
    float4 g1 = *(const float4*)(gamma + t * 8 + 4);
    float4 b0 = *(const float4*)(beta + t * 8);
    float4 b1 = *(const float4*)(beta + t * 8 + 4);
    float4 o0, o1;
    o0.x = (x0.x - mu) * inv * g0.x + b0.x;
    o0.y = (x0.y - mu) * inv * g0.y + b0.y;
    o0.z = (x0.z - mu) * inv * g0.z + b0.z;
    o0.w = (x0.w - mu) * inv * g0.w + b0.w;
    o1.x = (x1.x - mu) * inv * g1.x + b1.x;
    o1.y = (x1.y - mu) * inv * g1.y + b1.y;
    o1.z = (x1.z - mu) * inv * g1.z + b1.z;
    o1.w = (x1.w - mu) * inv * g1.w + b1.w;
    *(float4*)(out + (size_t)row * Cv + t * 8) = o0;
    *(float4*)(out + (size_t)row * Cv + t * 8 + 4) = o1;
}

// ---------------------------------------------------------------------------
extern "C" void kernel_launch(void* const* d_in, const int* in_sizes, int n_in,
                              void* d_out, int out_size)
{
    const float* x  = (const float*)d_in[0];
    const float* Wq = (const float*)d_in[1];
    const float* Wk = (const float*)d_in[2];
    const float* Wv = (const float*)d_in[3];
    const float* Wo = (const float*)d_in[4];
    const float* gm = (const float*)d_in[5];
    const float* bt = (const float*)d_in[6];
    float* out = (float*)d_out;

    float *qp, *kp, *vp, *ap, *pp, *xr, *wr;
    __nv_bfloat16 *khp, *klp, *vhp, *vlp;
    cudaGetSymbolAddress((void**)&qp, g_q);
    cudaGetSymbolAddress((void**)&kp, g_k);
    cudaGetSymbolAddress((void**)&vp, g_v);
    cudaGetSymbolAddress((void**)&ap, g_attn);
    cudaGetSymbolAddress((void**)&pp, g_proj);
    cudaGetSymbolAddress((void**)&xr, g_xr);
    cudaGetSymbolAddress((void**)&wr, g_wr);
    cudaGetSymbolAddress((void**)&khp, g_khi);
    cudaGetSymbolAddress((void**)&klp, g_klo);
    cudaGetSymbolAddress((void**)&vhp, g_vhi);
    cudaGetSymbolAddress((void**)&vlp, g_vlo);

    cudaFuncSetAttribute(flash_attn_bf16,
                         cudaFuncAttributeMaxDynamicSharedMemorySize,
                         FA_SMEM_BYTES);

    // pre-round x and weights to tf32 (rna), once
    const int nx4 = ROWS * Cv / 4;      // 2,097,152
    const int nw4 = Cv * Cv / 4;        // 1,048,576
    round_tf32_kernel<<<(nx4 + 255) / 256, 256>>>(x, xr, nx4);
    dim3 wgrid((nw4 + 255) / 256, 1, 4);
    round_tf32_w_kernel<<<wgrid, 256>>>(Wq, Wk, Wv, Wo, wr, nw4);

    dim3 qkvgrid(Cv / 128, ROWS / 128, 3);  // (16, 32, 3)
    tf32_gemm_qkv<<<qkvgrid, 256>>>(xr, wr, qp, kp, vp, ROWS, Cv, Cv);

    rope_split_kernel<<<Bv * Tv * Hv, 64>>>(qp, kp, vp, khp, klp, vhp, vlp);

    dim3 agrid(Tv / 64, Hv, Bv);  // (32, 16, 2)
    flash_attn_bf16<<<agrid, 256, FA_SMEM_BYTES>>>(qp, khp, klp, vhp, vlp, ap);

    dim3 ggrid(Cv / 128, ROWS / 128);  // (16, 32)
    tf32_gemm_nt<<<ggrid, 256>>>(ap, wr + (size_t)3 * Cv * Cv, pp, ROWS, Cv, Cv);
    layernorm_kernel<<<ROWS, 256>>>(pp, gm, bt, out);
}